// round 4
// baseline (speedup 1.0000x reference)
#include <cuda_runtime.h>
#include <cstdint>
#include <math_constants.h>

// Problem constants (fixed by setup_inputs)
#define B_ 4
#define C_ 3
#define M_ 4096
#define N_ 8192
#define K_ 16
#define NEIGH_TOTAL (B_ * C_ * M_ * K_)   // 786432

// Prepacked SoA point data: X, Y, Z coords and precomputed squared norm.
// 4 * 4 * 32768 B = 512 KB of __device__ globals (no allocation).
__device__ float g_PX[B_ * N_];
__device__ float g_PY[B_ * N_];
__device__ float g_PZ[B_ * N_];
__device__ float g_PW[B_ * N_];

// ---------------------------------------------------------------------------
// Prep: transpose points (B,C,N) -> SoA per batch, precompute |p|^2 with the
// same rounding as jnp.sum(p*p): mul, mul, mul, add, add (no FMA fusion).
// ---------------------------------------------------------------------------
__global__ void knn_prep_kernel(const float* __restrict__ points) {
    int t = blockIdx.x * blockDim.x + threadIdx.x;
    if (t >= B_ * N_) return;
    int b = t / N_;
    int n = t - b * N_;
    float x = points[(b * 3 + 0) * N_ + n];
    float y = points[(b * 3 + 1) * N_ + n];
    float z = points[(b * 3 + 2) * N_ + n];
    g_PX[t] = x;
    g_PY[t] = y;
    g_PZ[t] = z;
    float w = __fadd_rn(__fadd_rn(__fmul_rn(x, x), __fmul_rn(y, y)), __fmul_rn(z, z));
    g_PW[t] = w;
}

// ---------------------------------------------------------------------------
// Main KNN kernel: one warp per query. Warp-distributed sorted top-16 in
// lanes 0..15, shuffle-based insertion, lexicographic (dist, idx) ordering.
// ---------------------------------------------------------------------------
__global__ __launch_bounds__(256, 4) void knn_kernel(
    const float* __restrict__ query,
    float* __restrict__ out)
{
    const unsigned FULL = 0xFFFFFFFFu;
    const int warp = threadIdx.x >> 5;
    const int lane = threadIdx.x & 31;
    const int m = blockIdx.x * 8 + warp;   // query row
    const int b = blockIdx.y;              // batch

    // Query point (uniform across warp; broadcast load)
    const float qx = query[(b * 3 + 0) * M_ + m];
    const float qy = query[(b * 3 + 1) * M_ + m];
    const float qz = query[(b * 3 + 2) * M_ + m];
    // q2 like jnp.sum(q*q): mul-then-add, no contraction
    const float q2 = __fadd_rn(__fadd_rn(__fmul_rn(qx, qx), __fmul_rn(qy, qy)),
                               __fmul_rn(qz, qz));

    // Distributed sorted list: lane l (< 16) holds rank-l (dist, idx).
    float ld = CUDART_INF_F;
    int   li = 0x7FFFFFFF;
    // Replicated threshold = current rank-15 element
    float td = CUDART_INF_F;
    int   ti = 0x7FFFFFFF;

    const float4* __restrict__ PX4 = reinterpret_cast<const float4*>(g_PX + b * N_);
    const float4* __restrict__ PY4 = reinterpret_cast<const float4*>(g_PY + b * N_);
    const float4* __restrict__ PZ4 = reinterpret_cast<const float4*>(g_PZ + b * N_);
    const float4* __restrict__ PW4 = reinterpret_cast<const float4*>(g_PW + b * N_);

    for (int i = 0; i < N_ / 128; ++i) {       // 64 iterations, 128 points each
        const int v = i * 32 + lane;
        float4 x4 = PX4[v];
        float4 y4 = PY4[v];
        float4 z4 = PZ4[v];
        float4 w4 = PW4[v];
        const float px[4] = {x4.x, x4.y, x4.z, x4.w};
        const float py[4] = {y4.x, y4.y, y4.z, y4.w};
        const float pz[4] = {z4.x, z4.y, z4.z, z4.w};
        const float pw[4] = {w4.x, w4.y, w4.z, w4.w};

#pragma unroll
        for (int j = 0; j < 4; ++j) {
            // dot as FMA chain (XLA dot lowering); first product plain mul.
            float dot = __fmaf_rn(qz, pz[j],
                         __fmaf_rn(qy, py[j], __fmul_rn(qx, px[j])));
            // d = (q2 + p2) - 2*dot : the fma with exact -2*dot gives one
            // rounding, identical to (q2+p2) - (2*dot).
            float d = __fmaf_rn(-2.0f, dot, __fadd_rn(q2, pw[j]));

            // Candidate filter (<= catches ties; the insert resolves by index)
            bool ok = (d <= td);
            unsigned bal = __ballot_sync(FULL, ok);
            if (bal) {
                do {
                    const int src = __ffs(bal) - 1;
                    bal &= bal - 1;
                    const float cd = __shfl_sync(FULL, d, src);
                    const int   ci = (i * 32 + src) * 4 + j;

                    // Prune against (possibly stale within this chunk) threshold
                    if (cd > td || (cd == td && ci > ti)) continue;

                    // Distributed insert into sorted list (lanes 0..15)
                    bool lt = (ld < cd) || (ld == cd && li < ci);
                    unsigned mlt = __ballot_sync(FULL, lt) & 0xFFFFu;
                    int pos = __popc(mlt);
                    float pld = __shfl_up_sync(FULL, ld, 1);
                    int   pli = __shfl_up_sync(FULL, li, 1);
                    if (pos < 16) {
                        if (lane == pos)      { ld = cd;  li = ci;  }
                        else if (lane > pos)  { ld = pld; li = pli; }
                    }
                } while (bal);
                // Refresh replicated threshold once per triggered chunk
                td = __shfl_sync(FULL, ld, 15);
                ti = __shfl_sync(FULL, li, 15);
            }
        }
    }

    // Emit: lanes 0..15 hold the sorted top-16 (ascending dist, index tiebreak)
    if (lane < K_) {
        const int idx = li;
        const int pbase = b * N_ + idx;
        // neighbor_points: (B, C, M, K) float32
        out[((b * 3 + 0) * M_ + m) * K_ + lane] = g_PX[pbase];
        out[((b * 3 + 1) * M_ + m) * K_ + lane] = g_PY[pbase];
        out[((b * 3 + 2) * M_ + m) * K_ + lane] = g_PZ[pbase];
        // index_batch: (B, M, K), cast to float32 (exact for idx < 2^24)
        out[NEIGH_TOTAL + (b * M_ + m) * K_ + lane] = (float)idx;
    }
}

// ---------------------------------------------------------------------------
// Launcher
// ---------------------------------------------------------------------------
extern "C" void kernel_launch(void* const* d_in, const int* in_sizes, int n_in,
                              void* d_out, int out_size) {
    const float* query  = nullptr;
    const float* points = nullptr;
    for (int i = 0; i < n_in; ++i) {
        if (in_sizes[i] == B_ * C_ * M_)      query  = (const float*)d_in[i];
        else if (in_sizes[i] == B_ * C_ * N_) points = (const float*)d_in[i];
    }
    (void)out_size;

    knn_prep_kernel<<<(B_ * N_ + 255) / 256, 256>>>(points);
    dim3 grid(M_ / 8, B_);
    knn_kernel<<<grid, 256>>>(query, (float*)d_out);
}